// round 11
// baseline (speedup 1.0000x reference)
#include <cuda_runtime.h>
#include <math.h>

#define NN 50000
#define DD 64
#define EE 1250000
#define BB 4096
#define ROW4 16              // float4 per embedding row

// ---------------- scratch (device globals; no allocation) ----------------
__device__ float g_embA[NN * DD];
__device__ float g_embB[NN * DD];
__device__ float g_agg [NN * DD];
__device__ float g_ue[BB * 256];
__device__ float g_pe[BB * 256];
__device__ float g_ne[BB * 256];

// ---------------- tf32 helpers ----------------
__device__ __forceinline__ unsigned f2tf(float f) {
    unsigned r;
    asm("cvt.rna.tf32.f32 %0, %1;" : "=r"(r) : "f"(f));
    return r;
}
__device__ __forceinline__ void tfsplit(float f, unsigned& hi, unsigned& lo) {
    hi = f2tf(f);
    float r = f - __uint_as_float(hi);
    lo = f2tf(r);
}
__device__ __forceinline__ void mma_tf32(float* d, const unsigned* a,
                                         unsigned b0, unsigned b1) {
    asm volatile(
        "mma.sync.aligned.m16n8k8.row.col.f32.tf32.tf32.f32 "
        "{%0,%1,%2,%3},{%4,%5,%6,%7},{%8,%9},{%0,%1,%2,%3};"
        : "+f"(d[0]), "+f"(d[1]), "+f"(d[2]), "+f"(d[3])
        : "r"(a[0]), "r"(a[1]), "r"(a[2]), "r"(a[3]), "r"(b0), "r"(b1));
}

// ---------------- kernels ----------------

__global__ void zero_agg_kernel() {
    int i = blockIdx.x * blockDim.x + threadIdx.x;
    if (i < NN * DD / 4)
        reinterpret_cast<float4*>(g_agg)[i] = make_float4(0.f, 0.f, 0.f, 0.f);
}

// 16 threads per edge; one float4 chunk per thread; vector red scatter.
__global__ void spmm_kernel(const float* __restrict__ emb,
                            const float* __restrict__ vals,
                            const int*  __restrict__ rows,
                            const int*  __restrict__ cols) {
    unsigned gid = blockIdx.x * blockDim.x + threadIdx.x;
    unsigned e = gid >> 4;
    unsigned c = gid & 15u;
    if (e >= EE) return;
    int col = cols[e];
    int row = rows[e];
    float v = vals[e];
    float4 x = reinterpret_cast<const float4*>(emb)[(size_t)col * ROW4 + c];
    float4* dst = reinterpret_cast<float4*>(g_agg) + (size_t)row * ROW4 + c;
    asm volatile("red.global.add.v4.f32 [%0], {%1,%2,%3,%4};"
                 :: "l"(dst), "f"(v * x.x), "f"(v * x.y), "f"(v * x.z), "f"(v * x.w)
                 : "memory");
}

// ---------------- fused dense layer (tf32 MMA, quad-interleaved smem) ----------------
//   sx = (agg+emb) @ W1^T + b1
//   ox = agg * (emb @ W2^T + b2)
//   out = leaky_relu(sx + ox, 0.01)
// Block = 128 nodes x 64 outputs, 256 threads (8 warps).
// Warp = 32 rows x 32 j (4 row-groups x 2 j-groups).
// smem quads: sXq[n][k]=(xh,xl,axh,axl), sWq[j][k]=(w1h,w1l,w2h,w2l).
// Per ks per thread: 8 A-LDS.128 + 8 B-LDS.128 + 48 MMA, zero cvt.
#define BM 128
#define QS 68                                  // float4 stride per row
#define SQ_X 0                                 // float4 units
#define SQ_W (BM * QS)                         // 8704
#define F_B1 ((BM * QS + DD * QS) * 4)         // float index 52224
#define F_B2 (F_B1 + DD)
#define DSM_FLOATS (F_B2 + DD)                 // 52352 floats = 209408 B

__global__ void __launch_bounds__(256, 1) dense_kernel(
        const float* __restrict__ src,
        const float* __restrict__ w1,
        const float* __restrict__ b1,
        const float* __restrict__ w2,
        const float* __restrict__ b2,
        float* __restrict__ dst) {
    extern __shared__ float sm[];
    float4* sXq = reinterpret_cast<float4*>(sm) + SQ_X;
    float4* sWq = reinterpret_cast<float4*>(sm) + SQ_W;
    float* sB1 = sm + F_B1;
    float* sB2 = sm + F_B2;

    const int tid = threadIdx.x;
    const int base = blockIdx.x * BM;
    const int nrows = min(BM, NN - base);

    // ---- stage W quad: sWq[j][k] = (w1h, w1l, w2h, w2l) ----
    for (int idx = tid; idx < DD * DD; idx += 256) {
        int j = idx >> 6, k = idx & 63;
        unsigned h1, l1, h2, l2;
        tfsplit(w1[idx], h1, l1);
        tfsplit(w2[idx], h2, l2);
        sWq[j * QS + k] = make_float4(__uint_as_float(h1), __uint_as_float(l1),
                                      __uint_as_float(h2), __uint_as_float(l2));
    }
    if (tid < DD) { sB1[tid] = b1[tid]; sB2[tid] = b2[tid]; }

    // ---- stage X quad: sXq[n][k] = (xh, xl, axh, axl), zero-pad tail ----
    {
        const float4* srcv = reinterpret_cast<const float4*>(src);
        const float4* aggv = reinterpret_cast<const float4*>(g_agg);
        for (int idx = tid; idx < BM * ROW4; idx += 256) {
            int n = idx >> 4, c = idx & 15;
            float4 xv = make_float4(0.f, 0.f, 0.f, 0.f);
            float4 av = xv;
            if (n < nrows) {
                xv = srcv[(size_t)(base + n) * ROW4 + c];
                av = aggv[(size_t)(base + n) * ROW4 + c];
            }
            float xs[4] = { xv.x, xv.y, xv.z, xv.w };
            float as[4] = { xv.x + av.x, xv.y + av.y, xv.z + av.z, xv.w + av.w };
#pragma unroll
            for (int i = 0; i < 4; i++) {
                unsigned xh, xl, ah, al;
                tfsplit(xs[i], xh, xl);
                tfsplit(as[i], ah, al);
                sXq[n * QS + 4 * c + i] =
                    make_float4(__uint_as_float(xh), __uint_as_float(xl),
                                __uint_as_float(ah), __uint_as_float(al));
            }
        }
    }
    __syncthreads();

    const int wid  = tid >> 5;
    const int lane = tid & 31;
    const int g  = lane >> 2;      // 0..7
    const int tg = lane & 3;       // 0..3
    const int wr = wid & 3;        // row group: rows wr*32 .. wr*32+31
    const int wj = wid >> 2;       // j group: j wj*32 .. wj*32+31

    float acc1[2][4][4], acc2[2][4][4];
#pragma unroll
    for (int t = 0; t < 2; t++)
#pragma unroll
        for (int jt = 0; jt < 4; jt++)
#pragma unroll
            for (int p = 0; p < 4; p++) { acc1[t][jt][p] = 0.f; acc2[t][jt][p] = 0.f; }

#pragma unroll 2
    for (int ks = 0; ks < 8; ks++) {
        const int k0 = ks * 8;
        // ---- A fragments for 2 row tiles ----
        unsigned xh[2][4], xl[2][4], axh[2][4], axl[2][4];
#pragma unroll
        for (int t = 0; t < 2; t++) {
            const int r0 = wr * 32 + t * 16 + g;
            const int r1 = r0 + 8;
            float4 q0 = sXq[r0 * QS + k0 + tg];
            float4 q1 = sXq[r1 * QS + k0 + tg];
            float4 q2 = sXq[r0 * QS + k0 + tg + 4];
            float4 q3 = sXq[r1 * QS + k0 + tg + 4];
            xh [t][0] = __float_as_uint(q0.x); xl [t][0] = __float_as_uint(q0.y);
            axh[t][0] = __float_as_uint(q0.z); axl[t][0] = __float_as_uint(q0.w);
            xh [t][1] = __float_as_uint(q1.x); xl [t][1] = __float_as_uint(q1.y);
            axh[t][1] = __float_as_uint(q1.z); axl[t][1] = __float_as_uint(q1.w);
            xh [t][2] = __float_as_uint(q2.x); xl [t][2] = __float_as_uint(q2.y);
            axh[t][2] = __float_as_uint(q2.z); axl[t][2] = __float_as_uint(q2.w);
            xh [t][3] = __float_as_uint(q3.x); xl [t][3] = __float_as_uint(q3.y);
            axh[t][3] = __float_as_uint(q3.z); axl[t][3] = __float_as_uint(q3.w);
        }
        // ---- B fragments + MMAs per jt ----
#pragma unroll
        for (int jt = 0; jt < 4; jt++) {
            const int jb = wj * 32 + jt * 8 + g;
            float4 p0 = sWq[jb * QS + k0 + tg];
            float4 p1 = sWq[jb * QS + k0 + tg + 4];
            unsigned w1h0 = __float_as_uint(p0.x), w1l0 = __float_as_uint(p0.y);
            unsigned w2h0 = __float_as_uint(p0.z), w2l0 = __float_as_uint(p0.w);
            unsigned w1h1 = __float_as_uint(p1.x), w1l1 = __float_as_uint(p1.y);
            unsigned w2h1 = __float_as_uint(p1.z), w2l1 = __float_as_uint(p1.w);
#pragma unroll
            for (int t = 0; t < 2; t++) {
                mma_tf32(acc1[t][jt], axh[t], w1h0, w1h1);
                mma_tf32(acc1[t][jt], axh[t], w1l0, w1l1);
                mma_tf32(acc1[t][jt], axl[t], w1h0, w1h1);
                mma_tf32(acc2[t][jt], xh[t],  w2h0, w2h1);
                mma_tf32(acc2[t][jt], xh[t],  w2l0, w2l1);
                mma_tf32(acc2[t][jt], xl[t],  w2h0, w2h1);
            }
        }
    }

    // ---- epilogue: agg = (axh+axl)-(xh+xl), bias, elementwise, leaky, store ----
#pragma unroll
    for (int t = 0; t < 2; t++) {
        const int row0 = wr * 32 + t * 16 + g;
        const int row1 = row0 + 8;
#pragma unroll
        for (int jt = 0; jt < 4; jt++) {
            const int j = wj * 32 + jt * 8 + tg * 2;
            float bj0 = sB1[j], bj1 = sB1[j + 1];
            float cj0 = sB2[j], cj1 = sB2[j + 1];
            if (row0 < nrows) {
                float4 qa = sXq[row0 * QS + j];
                float4 qb = sXq[row0 * QS + j + 1];
                float ag0 = (qa.z + qa.w) - (qa.x + qa.y);
                float ag1 = (qb.z + qb.w) - (qb.x + qb.y);
                float v0 = (acc1[t][jt][0] + bj0) + ag0 * (acc2[t][jt][0] + cj0);
                float v1 = (acc1[t][jt][1] + bj1) + ag1 * (acc2[t][jt][1] + cj1);
                v0 = v0 > 0.f ? v0 : 0.01f * v0;
                v1 = v1 > 0.f ? v1 : 0.01f * v1;
                *reinterpret_cast<float2*>(dst + (size_t)(base + row0) * DD + j) =
                    make_float2(v0, v1);
            }
            if (row1 < nrows) {
                float4 qa = sXq[row1 * QS + j];
                float4 qb = sXq[row1 * QS + j + 1];
                float ag0 = (qa.z + qa.w) - (qa.x + qa.y);
                float ag1 = (qb.z + qb.w) - (qb.x + qb.y);
                float v0 = (acc1[t][jt][2] + bj0) + ag0 * (acc2[t][jt][2] + cj0);
                float v1 = (acc1[t][jt][3] + bj1) + ag1 * (acc2[t][jt][3] + cj1);
                v0 = v0 > 0.f ? v0 : 0.01f * v0;
                v1 = v1 > 0.f ? v1 : 0.01f * v1;
                *reinterpret_cast<float2*>(dst + (size_t)(base + row1) * DD + j) =
                    make_float2(v0, v1);
            }
        }
    }
}

// ---------------- gather + loss ----------------

__global__ void gather_kernel(const float* __restrict__ emb,
                              const int* __restrict__ user,
                              const int* __restrict__ pos,
                              const int* __restrict__ neg,
                              int layer) {
    unsigned t = blockIdx.x * blockDim.x + threadIdx.x;
    if (t >= BB * 16) return;
    unsigned i = t >> 4;
    unsigned c = t & 15u;
    unsigned doff = i * 64 + (unsigned)layer * 16 + c;
    const float4* ev = reinterpret_cast<const float4*>(emb);
    reinterpret_cast<float4*>(g_ue)[doff] = ev[(size_t)user[i] * ROW4 + c];
    reinterpret_cast<float4*>(g_pe)[doff] = ev[(size_t)pos [i] * ROW4 + c];
    reinterpret_cast<float4*>(g_ne)[doff] = ev[(size_t)neg [i] * ROW4 + c];
}

__global__ void zero_out_kernel(float* out) {
    if (threadIdx.x == 0 && blockIdx.x == 0) out[0] = 0.f;
}

__global__ void loss_kernel(float* __restrict__ out) {
    int i = blockIdx.x * blockDim.x + threadIdx.x;
    float dp = 0.f, dn = 0.f;
    if (i < BB) {
        const float4* uv = reinterpret_cast<const float4*>(g_ue);
        const float4* pv = reinterpret_cast<const float4*>(g_pe);
        const float4* nv = reinterpret_cast<const float4*>(g_ne);
#pragma unroll 8
        for (int c = 0; c < 64; c++) {
            float4 u = uv[(size_t)i * 64 + c];
            float4 p = pv[(size_t)i * 64 + c];
            float4 q = nv[(size_t)i * 64 + c];
            dp += u.x*p.x + u.y*p.y + u.z*p.z + u.w*p.w;
            dn += u.x*q.x + u.y*q.y + u.z*q.z + u.w*q.w;
        }
    }
    float d = dp - dn;
    float l = (i < BB) ? (fmaxf(-d, 0.f) + log1pf(expf(-fabsf(d)))) : 0.f;

    __shared__ float red[256];
    red[threadIdx.x] = l;
    __syncthreads();
    for (int s = 128; s > 0; s >>= 1) {
        if (threadIdx.x < s) red[threadIdx.x] += red[threadIdx.x + s];
        __syncthreads();
    }
    if (threadIdx.x == 0) atomicAdd(out, red[0]);
}

// ---------------- launch ----------------

extern "C" void kernel_launch(void* const* d_in, const int* in_sizes, int n_in,
                              void* d_out, int out_size) {
    const float* emb  = (const float*)d_in[0];
    const float* w1w  = (const float*)d_in[1];
    const float* w1b  = (const float*)d_in[2];
    const float* w2w  = (const float*)d_in[3];
    const float* w2b  = (const float*)d_in[4];
    const float* vals = (const float*)d_in[5];
    const int*   rows = (const int*)d_in[6];
    const int*   cols = (const int*)d_in[7];
    const int*   user = (const int*)d_in[8];
    const int*   pos  = (const int*)d_in[9];
    const int*   neg  = (const int*)d_in[10];
    float* out = (float*)d_out;

    void *pA = nullptr, *pB = nullptr;
    cudaGetSymbolAddress(&pA, g_embA);
    cudaGetSymbolAddress(&pB, g_embB);
    float* eA = (float*)pA;
    float* eB = (float*)pB;

    const int SMEM_BYTES = DSM_FLOATS * 4;   // 209408
    cudaFuncSetAttribute(dense_kernel,
                         cudaFuncAttributeMaxDynamicSharedMemorySize, SMEM_BYTES);

    const int ZB = (NN * DD / 4 + 255) / 256;
    const int SB = (EE * 16) / 256;           // 78125 exact
    const int DB = (NN + BM - 1) / BM;        // 391
    const int GB = (BB * 16 + 255) / 256;

    // layer 0 input gather
    gather_kernel<<<GB, 256>>>(emb, user, pos, neg, 0);

    // layer 1: emb -> eA
    zero_agg_kernel<<<ZB, 256>>>();
    spmm_kernel<<<SB, 256>>>(emb, vals, rows, cols);
    dense_kernel<<<DB, 256, SMEM_BYTES>>>(emb, w1w, w1b, w2w, w2b, eA);
    gather_kernel<<<GB, 256>>>(eA, user, pos, neg, 1);

    // layer 2: eA -> eB
    zero_agg_kernel<<<ZB, 256>>>();
    spmm_kernel<<<SB, 256>>>(eA, vals, rows, cols);
    dense_kernel<<<DB, 256, SMEM_BYTES>>>(eA, w1w + 4096, w1b + 64, w2w + 4096, w2b + 64, eB);
    gather_kernel<<<GB, 256>>>(eB, user, pos, neg, 2);

    // layer 3: eB -> eA
    zero_agg_kernel<<<ZB, 256>>>();
    spmm_kernel<<<SB, 256>>>(eB, vals, rows, cols);
    dense_kernel<<<DB, 256, SMEM_BYTES>>>(eB, w1w + 8192, w1b + 128, w2w + 8192, w2b + 128, eA);
    gather_kernel<<<GB, 256>>>(eA, user, pos, neg, 3);

    // loss
    zero_out_kernel<<<1, 32>>>(out);
    loss_kernel<<<BB / 256, 256>>>(out);
}

// round 13
// speedup vs baseline: 1.0655x; 1.0655x over previous
#include <cuda_runtime.h>
#include <math.h>

#define NN 50000
#define DD 64
#define EE 1250000
#define BB 4096
#define ROW4 16              // float4 per embedding row

// ---------------- scratch (device globals; no allocation) ----------------
__device__ float g_embA[NN * DD];
__device__ float g_embB[NN * DD];
__device__ float g_agg [NN * DD];
__device__ float g_ue[BB * 256];
__device__ float g_pe[BB * 256];
__device__ float g_ne[BB * 256];

// ---------------- tf32 helpers ----------------
__device__ __forceinline__ unsigned f2tf(float f) {
    unsigned r;
    asm("cvt.rna.tf32.f32 %0, %1;" : "=r"(r) : "f"(f));
    return r;
}
__device__ __forceinline__ void tfsplit(float f, unsigned& hi, unsigned& lo) {
    hi = f2tf(f);
    float r = f - __uint_as_float(hi);
    lo = f2tf(r);
}
__device__ __forceinline__ void mma_tf32(float* d, const unsigned* a,
                                         unsigned b0, unsigned b1) {
    asm volatile(
        "mma.sync.aligned.m16n8k8.row.col.f32.tf32.tf32.f32 "
        "{%0,%1,%2,%3},{%4,%5,%6,%7},{%8,%9},{%0,%1,%2,%3};"
        : "+f"(d[0]), "+f"(d[1]), "+f"(d[2]), "+f"(d[3])
        : "r"(a[0]), "r"(a[1]), "r"(a[2]), "r"(a[3]), "r"(b0), "r"(b1));
}

// ---------------- kernels ----------------

__global__ void zero_agg_kernel() {
    int i = blockIdx.x * blockDim.x + threadIdx.x;
    if (i < NN * DD / 4)
        reinterpret_cast<float4*>(g_agg)[i] = make_float4(0.f, 0.f, 0.f, 0.f);
}

// 16 threads per edge; one float4 chunk per thread; vector red scatter.
__global__ void spmm_kernel(const float* __restrict__ emb,
                            const float* __restrict__ vals,
                            const int*  __restrict__ rows,
                            const int*  __restrict__ cols) {
    unsigned gid = blockIdx.x * blockDim.x + threadIdx.x;
    unsigned e = gid >> 4;
    unsigned c = gid & 15u;
    if (e >= EE) return;
    int col = cols[e];
    int row = rows[e];
    float v = vals[e];
    float4 x = reinterpret_cast<const float4*>(emb)[(size_t)col * ROW4 + c];
    float4* dst = reinterpret_cast<float4*>(g_agg) + (size_t)row * ROW4 + c;
    asm volatile("red.global.add.v4.f32 [%0], {%1,%2,%3,%4};"
                 :: "l"(dst), "f"(v * x.x), "f"(v * x.y), "f"(v * x.z), "f"(v * x.w)
                 : "memory");
}

// ---------------- fused dense layer (tf32 MMA, 2 blocks/SM) ----------------
//   sx = (agg+emb) @ W1^T + b1
//   ox = agg * (emb @ W2^T + b2)
//   out = leaky_relu(sx + ox, 0.01)
// Block = 64 nodes x 64 outputs, 256 threads (8 warps), 2 blocks/SM.
// Warp = 16 rows x 32 j (4 row groups x 2 j halves).
// smem float2 pairs: sXA[n][k]=(x, x+agg), sW[j][k]=(w_hi, w_lo).
// 3-product tf32 split for fp32-grade precision (rel_err ~3e-7).
#define BM 64
#define WS2 70                                  // float2 stride per row
#define NF2 (BM * WS2)                          // 4480 float2 per plane
#define F_B1 (3 * NF2 * 2)                      // float index 26880
#define F_B2 (F_B1 + DD)
#define DSM_FLOATS (F_B2 + DD)                  // 27008 floats = 108032 B

__global__ void __launch_bounds__(256, 2) dense_kernel(
        const float* __restrict__ src,
        const float* __restrict__ w1,
        const float* __restrict__ b1,
        const float* __restrict__ w2,
        const float* __restrict__ b2,
        float* __restrict__ dst) {
    extern __shared__ float sm[];
    float2* sXA = reinterpret_cast<float2*>(sm);
    float2* sW1 = sXA + NF2;
    float2* sW2 = sW1 + NF2;
    float* sB1 = sm + F_B1;
    float* sB2 = sm + F_B2;

    const int tid = threadIdx.x;
    const int base = blockIdx.x * BM;
    const int nrows = min(BM, NN - base);

    // ---- stage W split (hi,lo) pairs: sW[j][k] = (wh, wl) ----
    for (int idx = tid; idx < DD * DD; idx += 256) {
        int j = idx >> 6, k = idx & 63;
        unsigned h, l;
        tfsplit(w1[idx], h, l);
        sW1[j * WS2 + k] = make_float2(__uint_as_float(h), __uint_as_float(l));
        tfsplit(w2[idx], h, l);
        sW2[j * WS2 + k] = make_float2(__uint_as_float(h), __uint_as_float(l));
    }
    if (tid < DD) { sB1[tid] = b1[tid]; sB2[tid] = b2[tid]; }

    // ---- stage XA pairs: sXA[n][k] = (x, x+agg), zero-pad tail rows ----
    {
        const float4* srcv = reinterpret_cast<const float4*>(src);
        const float4* aggv = reinterpret_cast<const float4*>(g_agg);
        for (int idx = tid; idx < BM * ROW4; idx += 256) {
            int n = idx >> 4, c = idx & 15;
            float4 xv = make_float4(0.f, 0.f, 0.f, 0.f);
            float4 av = xv;
            if (n < nrows) {
                xv = srcv[(size_t)(base + n) * ROW4 + c];
                av = aggv[(size_t)(base + n) * ROW4 + c];
            }
            float2* p = sXA + n * WS2 + 4 * c;
            p[0] = make_float2(xv.x, xv.x + av.x);
            p[1] = make_float2(xv.y, xv.y + av.y);
            p[2] = make_float2(xv.z, xv.z + av.z);
            p[3] = make_float2(xv.w, xv.w + av.w);
        }
    }
    __syncthreads();

    const int wid  = tid >> 5;
    const int lane = tid & 31;
    const int g  = lane >> 2;      // 0..7
    const int tg = lane & 3;       // 0..3
    const int wr = wid & 3;        // row group: rows wr*16 .. wr*16+15
    const int wj = wid >> 2;       // j half: j wj*32 .. wj*32+31
    const int n0 = wr * 16;

    float acc1[4][4], acc2[4][4];
#pragma unroll
    for (int jt = 0; jt < 4; jt++)
#pragma unroll
        for (int p = 0; p < 4; p++) { acc1[jt][p] = 0.f; acc2[jt][p] = 0.f; }

#pragma unroll 2
    for (int ks = 0; ks < 8; ks++) {
        const int k0 = ks * 8;
        // ---- A fragments (m16k8 row-major) ----
        // positions: (g,tg) (g+8,tg) (g,tg+4) (g+8,tg+4)
        unsigned xh[4], xl[4], axh[4], axl[4];
        {
            float2 q0 = sXA[(n0 + g)     * WS2 + k0 + tg];
            float2 q1 = sXA[(n0 + g + 8) * WS2 + k0 + tg];
            float2 q2 = sXA[(n0 + g)     * WS2 + k0 + tg + 4];
            float2 q3 = sXA[(n0 + g + 8) * WS2 + k0 + tg + 4];
            tfsplit(q0.x, xh[0], xl[0]); tfsplit(q0.y, axh[0], axl[0]);
            tfsplit(q1.x, xh[1], xl[1]); tfsplit(q1.y, axh[1], axl[1]);
            tfsplit(q2.x, xh[2], xl[2]); tfsplit(q2.y, axh[2], axl[2]);
            tfsplit(q3.x, xh[3], xl[3]); tfsplit(q3.y, axh[3], axl[3]);
        }
        // ---- B fragments + MMAs per jt ----
#pragma unroll
        for (int jt = 0; jt < 4; jt++) {
            const int jb = wj * 32 + jt * 8 + g;
            float2 p10 = sW1[jb * WS2 + k0 + tg];
            float2 p11 = sW1[jb * WS2 + k0 + tg + 4];
            float2 p20 = sW2[jb * WS2 + k0 + tg];
            float2 p21 = sW2[jb * WS2 + k0 + tg + 4];
            unsigned w1h0 = __float_as_uint(p10.x), w1l0 = __float_as_uint(p10.y);
            unsigned w1h1 = __float_as_uint(p11.x), w1l1 = __float_as_uint(p11.y);
            unsigned w2h0 = __float_as_uint(p20.x), w2l0 = __float_as_uint(p20.y);
            unsigned w2h1 = __float_as_uint(p21.x), w2l1 = __float_as_uint(p21.y);
            mma_tf32(acc1[jt], axh, w1h0, w1h1);
            mma_tf32(acc1[jt], axh, w1l0, w1l1);
            mma_tf32(acc1[jt], axl, w1h0, w1h1);
            mma_tf32(acc2[jt], xh,  w2h0, w2h1);
            mma_tf32(acc2[jt], xh,  w2l0, w2l1);
            mma_tf32(acc2[jt], xl,  w2h0, w2h1);
        }
    }

    // ---- epilogue: agg = ax - x, bias, elementwise, leaky-relu, store ----
    const int row0 = n0 + g;
    const int row1 = row0 + 8;
#pragma unroll
    for (int jt = 0; jt < 4; jt++) {
        const int j = wj * 32 + jt * 8 + tg * 2;
        float bj0 = sB1[j], bj1 = sB1[j + 1];
        float cj0 = sB2[j], cj1 = sB2[j + 1];
        if (row0 < nrows) {
            float2 qa = sXA[row0 * WS2 + j];
            float2 qb = sXA[row0 * WS2 + j + 1];
            float ag0 = qa.y - qa.x;
            float ag1 = qb.y - qb.x;
            float v0 = (acc1[jt][0] + bj0) + ag0 * (acc2[jt][0] + cj0);
            float v1 = (acc1[jt][1] + bj1) + ag1 * (acc2[jt][1] + cj1);
            v0 = v0 > 0.f ? v0 : 0.01f * v0;
            v1 = v1 > 0.f ? v1 : 0.01f * v1;
            *reinterpret_cast<float2*>(dst + (size_t)(base + row0) * DD + j) =
                make_float2(v0, v1);
        }
        if (row1 < nrows) {
            float2 qa = sXA[row1 * WS2 + j];
            float2 qb = sXA[row1 * WS2 + j + 1];
            float ag0 = qa.y - qa.x;
            float ag1 = qb.y - qb.x;
            float v0 = (acc1[jt][2] + bj0) + ag0 * (acc2[jt][2] + cj0);
            float v1 = (acc1[jt][3] + bj1) + ag1 * (acc2[jt][3] + cj1);
            v0 = v0 > 0.f ? v0 : 0.01f * v0;
            v1 = v1 > 0.f ? v1 : 0.01f * v1;
            *reinterpret_cast<float2*>(dst + (size_t)(base + row1) * DD + j) =
                make_float2(v0, v1);
        }
    }
}

// ---------------- gather + loss ----------------

__global__ void gather_kernel(const float* __restrict__ emb,
                              const int* __restrict__ user,
                              const int* __restrict__ pos,
                              const int* __restrict__ neg,
                              int layer) {
    unsigned t = blockIdx.x * blockDim.x + threadIdx.x;
    if (t >= BB * 16) return;
    unsigned i = t >> 4;
    unsigned c = t & 15u;
    unsigned doff = i * 64 + (unsigned)layer * 16 + c;
    const float4* ev = reinterpret_cast<const float4*>(emb);
    reinterpret_cast<float4*>(g_ue)[doff] = ev[(size_t)user[i] * ROW4 + c];
    reinterpret_cast<float4*>(g_pe)[doff] = ev[(size_t)pos [i] * ROW4 + c];
    reinterpret_cast<float4*>(g_ne)[doff] = ev[(size_t)neg [i] * ROW4 + c];
}

__global__ void zero_out_kernel(float* out) {
    if (threadIdx.x == 0 && blockIdx.x == 0) out[0] = 0.f;
}

__global__ void loss_kernel(float* __restrict__ out) {
    int i = blockIdx.x * blockDim.x + threadIdx.x;
    float dp = 0.f, dn = 0.f;
    if (i < BB) {
        const float4* uv = reinterpret_cast<const float4*>(g_ue);
        const float4* pv = reinterpret_cast<const float4*>(g_pe);
        const float4* nv = reinterpret_cast<const float4*>(g_ne);
#pragma unroll 8
        for (int c = 0; c < 64; c++) {
            float4 u = uv[(size_t)i * 64 + c];
            float4 p = pv[(size_t)i * 64 + c];
            float4 q = nv[(size_t)i * 64 + c];
            dp += u.x*p.x + u.y*p.y + u.z*p.z + u.w*p.w;
            dn += u.x*q.x + u.y*q.y + u.z*q.z + u.w*q.w;
        }
    }
    float d = dp - dn;
    float l = (i < BB) ? (fmaxf(-d, 0.f) + log1pf(expf(-fabsf(d)))) : 0.f;

    __shared__ float red[256];
    red[threadIdx.x] = l;
    __syncthreads();
    for (int s = 128; s > 0; s >>= 1) {
        if (threadIdx.x < s) red[threadIdx.x] += red[threadIdx.x + s];
        __syncthreads();
    }
    if (threadIdx.x == 0) atomicAdd(out, red[0]);
}

// ---------------- launch ----------------

extern "C" void kernel_launch(void* const* d_in, const int* in_sizes, int n_in,
                              void* d_out, int out_size) {
    const float* emb  = (const float*)d_in[0];
    const float* w1w  = (const float*)d_in[1];
    const float* w1b  = (const float*)d_in[2];
    const float* w2w  = (const float*)d_in[3];
    const float* w2b  = (const float*)d_in[4];
    const float* vals = (const float*)d_in[5];
    const int*   rows = (const int*)d_in[6];
    const int*   cols = (const int*)d_in[7];
    const int*   user = (const int*)d_in[8];
    const int*   pos  = (const int*)d_in[9];
    const int*   neg  = (const int*)d_in[10];
    float* out = (float*)d_out;

    void *pA = nullptr, *pB = nullptr;
    cudaGetSymbolAddress(&pA, g_embA);
    cudaGetSymbolAddress(&pB, g_embB);
    float* eA = (float*)pA;
    float* eB = (float*)pB;

    const int SMEM_BYTES = DSM_FLOATS * 4;   // 108032
    cudaFuncSetAttribute(dense_kernel,
                         cudaFuncAttributeMaxDynamicSharedMemorySize, SMEM_BYTES);

    const int ZB = (NN * DD / 4 + 255) / 256;
    const int SB = (EE * 16) / 256;           // 78125 exact
    const int DB = (NN + BM - 1) / BM;        // 782
    const int GB = (BB * 16 + 255) / 256;

    // layer 0 input gather
    gather_kernel<<<GB, 256>>>(emb, user, pos, neg, 0);

    // layer 1: emb -> eA
    zero_agg_kernel<<<ZB, 256>>>();
    spmm_kernel<<<SB, 256>>>(emb, vals, rows, cols);
    dense_kernel<<<DB, 256, SMEM_BYTES>>>(emb, w1w, w1b, w2w, w2b, eA);
    gather_kernel<<<GB, 256>>>(eA, user, pos, neg, 1);

    // layer 2: eA -> eB
    zero_agg_kernel<<<ZB, 256>>>();
    spmm_kernel<<<SB, 256>>>(eA, vals, rows, cols);
    dense_kernel<<<DB, 256, SMEM_BYTES>>>(eA, w1w + 4096, w1b + 64, w2w + 4096, w2b + 64, eB);
    gather_kernel<<<GB, 256>>>(eB, user, pos, neg, 2);

    // layer 3: eB -> eA
    zero_agg_kernel<<<ZB, 256>>>();
    spmm_kernel<<<SB, 256>>>(eB, vals, rows, cols);
    dense_kernel<<<DB, 256, SMEM_BYTES>>>(eB, w1w + 8192, w1b + 128, w2w + 8192, w2b + 128, eA);
    gather_kernel<<<GB, 256>>>(eA, user, pos, neg, 3);

    // loss
    zero_out_kernel<<<1, 32>>>(out);
    loss_kernel<<<BB / 256, 256>>>(out);
}